// round 7
// baseline (speedup 1.0000x reference)
#include <cuda_runtime.h>
#include <cuda_bf16.h>
#include <cstdint>

// PairExcludeMask: out[f,i,n] = type_mask[ atype[f,i]*9 + tj ]
//   tj = (nlist[f,i,n] == -1) ? 8 : atype[f, nlist[f,i,n]]
//
// pack_kernel: per atom j, byte B[j] with bit ti = (type_mask[ti*9+type_j] != 0).
// mask_kernel: 32KB per-frame byte table in DYNAMIC smem (carveout raised so
// smem never caps occupancy). One warp per row -> warp-uniform m = 1<<ti.
// All-pass / all-fail rows are written as constants without reading nlist.
// Slow path per neighbor: LDS.U8; (B & m) ? 1.0f : 0.0f.

static constexpr int NF     = 4;
static constexpr int NLOC   = 16384;
static constexpr int NNEI   = 128;
static constexpr int NALL   = 32768;
static constexpr int NTYPES = 8;
static constexpr int TM1    = NTYPES + 1;          // 9
static constexpr uint32_t FULL = (1u << TM1) - 1;  // 0x1FF
static constexpr uint32_t ONEF = 0x3F800000u;      // 1.0f bits

static constexpr int TBL_BYTES = NALL + 16;        // + virtual atom + pad

__device__ __align__(16) uint8_t g_byte[NF][TBL_BYTES];

// ---------------- kernel 1: per-atom mask byte ----------------
__global__ __launch_bounds__(256)
void pack_kernel(const int* __restrict__ atype, const float* __restrict__ tmask)
{
    __shared__ uint32_t s_tb[16];                  // per-type mask byte
    if (threadIdx.x < TM1) {
        uint32_t b = 0;
        #pragma unroll
        for (int ti = 0; ti < NTYPES; ++ti)        // centers have ti < 8
            b |= (tmask[ti * TM1 + threadIdx.x] != 0.0f ? 1u : 0u) << ti;
        s_tb[threadIdx.x] = b;
    }
    __syncthreads();

    const int idx = blockIdx.x * 256 + threadIdx.x;   // over NF*NALL/16
    const int f   = idx >> 11;                        // / (NALL/16)
    const int wi  = idx & (NALL / 16 - 1);
    const int4* __restrict__ at4 = (const int4*)(atype + f * NALL);

    uint4 o;
    uint32_t* po = &o.x;
    #pragma unroll
    for (int q = 0; q < 4; ++q) {
        int4 a = at4[wi * 4 + q];
        po[q] = s_tb[a.x] | (s_tb[a.y] << 8) | (s_tb[a.z] << 16) | (s_tb[a.w] << 24);
    }
    ((uint4*)g_byte[f])[wi] = o;

    if (wi == 0) {                                 // virtual atom j == NALL
        uint32_t v = s_tb[NTYPES];                 // byte for type-8 virtual nbr
        #pragma unroll
        for (int k = 0; k < 16; ++k)
            g_byte[f][NALL + k] = (uint8_t)(k == 0 ? v : 0);
    }
}

// ---------------- kernel 2: stream the mask ----------------
static constexpr int THREADS_B = 512;
static constexpr int BPF       = 128;                      // blocks per frame
static constexpr int ROWS_PB   = NLOC / BPF;               // 128 rows / block
static constexpr int ROW_VEC   = NNEI / 4;                 // 32 vec4 per row
static constexpr int VEC_PB    = ROWS_PB * ROW_VEC;        // 4096
static constexpr int BATCH     = 4;
static constexpr int NBATCH    = VEC_PB / (THREADS_B * BATCH);  // 2
static constexpr int BLOCKS_B  = NF * BPF;                 // 512

static constexpr int SMEM_DYN  = TBL_BYTES;                // 32.8 KB

__global__ __launch_bounds__(THREADS_B)
void mask_kernel(const int4* __restrict__ nlist4,
                 const int*  __restrict__ atype,
                 const float* __restrict__ tmask,
                 uint4* __restrict__ out4)
{
    extern __shared__ uint8_t s_byte[];            // [TBL_BYTES] mask bytes
    __shared__ uint32_t s_rw[16];                  // per-type 9-bit row word
    __shared__ uint32_t s_rowinfo[ROWS_PB];        // (flag<<16) | (1<<ti)

    const int tid  = threadIdx.x;
    const int f    = blockIdx.x >> 7;              // / BPF
    const int row0 = (blockIdx.x & (BPF - 1)) * ROWS_PB;

    // coalesced 16B copy of the byte table from L2
    {
        const uint4* __restrict__ src = (const uint4*)g_byte[f];
        uint4* dst = (uint4*)s_byte;
        #pragma unroll
        for (int k = tid; k < TBL_BYTES / 16; k += THREADS_B)
            dst[k] = src[k];
    }
    if (tid < TM1) {
        uint32_t w = 0;
        #pragma unroll
        for (int tj = 0; tj < TM1; ++tj)
            w |= (tmask[tid * TM1 + tj] != 0.0f ? 1u : 0u) << tj;
        s_rw[tid] = w;
    }
    __syncthreads();
    if (tid < ROWS_PB) {
        const int ti = __ldg(atype + f * NALL + row0 + tid);
        const uint32_t rw = s_rw[ti];
        const uint32_t flag = (rw == FULL) ? 1u : ((rw == 0u) ? 0u : 2u);
        s_rowinfo[tid] = (flag << 16) | (1u << ti);
    }
    __syncthreads();

    const size_t base = ((size_t)f * NLOC + row0) * ROW_VEC;
    const int4*  __restrict__ nl = nlist4 + base;
    uint4*       __restrict__ ob = out4  + base;

    #pragma unroll
    for (int b = 0; b < NBATCH; ++b) {
        uint32_t info[BATCH];
        int4     nj[BATCH];

        #pragma unroll
        for (int k = 0; k < BATCH; ++k)
            info[k] = s_rowinfo[(tid + (b * BATCH + k) * THREADS_B) >> 5];

        #pragma unroll
        for (int k = 0; k < BATCH; ++k)
            if ((info[k] >> 16) == 2u)
                nj[k] = nl[tid + (b * BATCH + k) * THREADS_B];

        #pragma unroll
        for (int k = 0; k < BATCH; ++k) {
            const int v = tid + (b * BATCH + k) * THREADS_B;
            const uint32_t flag = info[k] >> 16;

            if (flag == 1u) { ob[v] = make_uint4(ONEF, ONEF, ONEF, ONEF); continue; }
            if (flag == 0u) { ob[v] = make_uint4(0u, 0u, 0u, 0u);         continue; }

            const uint32_t m = info[k] & 0xFFFFu;  // 1 << ti (warp-uniform)

            uint32_t j0 = min((uint32_t)nj[k].x, (uint32_t)NALL);
            uint32_t j1 = min((uint32_t)nj[k].y, (uint32_t)NALL);
            uint32_t j2 = min((uint32_t)nj[k].z, (uint32_t)NALL);
            uint32_t j3 = min((uint32_t)nj[k].w, (uint32_t)NALL);

            uint32_t b0 = s_byte[j0];
            uint32_t b1 = s_byte[j1];
            uint32_t b2 = s_byte[j2];
            uint32_t b3 = s_byte[j3];

            uint4 r;
            r.x = (b0 & m) ? ONEF : 0u;
            r.y = (b1 & m) ? ONEF : 0u;
            r.z = (b2 & m) ? ONEF : 0u;
            r.w = (b3 & m) ? ONEF : 0u;

            ob[v] = r;
        }
    }
}

extern "C" void kernel_launch(void* const* d_in, const int* in_sizes, int n_in,
                              void* d_out, int out_size)
{
    const int4*  nlist4 = (const int4*) d_in[0];
    const int*   atype  = (const int*)  d_in[1];
    const float* tmask  = (const float*)d_in[2];
    // d_in[3] = ntypes scalar (8, baked into constants)

    uint4* out4 = (uint4*)d_out;

    static bool configured = false;
    if (!configured) {
        cudaFuncSetAttribute(mask_kernel,
                             cudaFuncAttributeMaxDynamicSharedMemorySize,
                             SMEM_DYN);
        cudaFuncSetAttribute(mask_kernel,
                             cudaFuncAttributePreferredSharedMemoryCarveout,
                             100);   // max smem carveout -> smem never caps occ
        configured = true;
    }

    pack_kernel<<<NF * NALL / 16 / 256, 256>>>(atype, tmask);
    mask_kernel<<<BLOCKS_B, THREADS_B, SMEM_DYN>>>(nlist4, atype, tmask, out4);
}

// round 8
// speedup vs baseline: 1.0173x; 1.0173x over previous
#include <cuda_runtime.h>
#include <cuda_bf16.h>
#include <cstdint>

// PairExcludeMask: out[f,i,n] = type_mask[ atype[f,i]*9 + tj ]
//   tj = (nlist[f,i,n] == -1) ? 8 : atype[f, nlist[f,i,n]]
//
// pack_kernel: per atom j, byte B[j] with bit ti = (type_mask[ti*9+type_j] != 0).
// mask_kernel: 32KB per-frame byte table in dynamic smem; one warp per row ->
// warp-uniform m = 1<<ti. All-pass/all-fail rows are written as constants
// without reading nlist. Slow path: LDS.U8; (B & m) ? 1.0f : 0.0f.
// Structure: deep (8x) per-thread prefetch of nlist + overlapped prologue to
// avoid the post-barrier lockstep LDG burst that left warps latency-bound.

static constexpr int NF     = 4;
static constexpr int NLOC   = 16384;
static constexpr int NNEI   = 128;
static constexpr int NALL   = 32768;
static constexpr int NTYPES = 8;
static constexpr int TM1    = NTYPES + 1;          // 9
static constexpr uint32_t FULL = (1u << TM1) - 1;  // 0x1FF
static constexpr uint32_t ONEF = 0x3F800000u;      // 1.0f bits

static constexpr int TBL_BYTES = NALL + 16;        // + virtual atom + pad

__device__ __align__(16) uint8_t g_byte[NF][TBL_BYTES];

// ---------------- kernel 1: per-atom mask byte ----------------
__global__ __launch_bounds__(256)
void pack_kernel(const int* __restrict__ atype, const float* __restrict__ tmask)
{
    __shared__ uint32_t s_tb[16];                  // per-type mask byte
    if (threadIdx.x < TM1) {
        uint32_t b = 0;
        #pragma unroll
        for (int ti = 0; ti < NTYPES; ++ti)        // centers have ti < 8
            b |= (tmask[ti * TM1 + threadIdx.x] != 0.0f ? 1u : 0u) << ti;
        s_tb[threadIdx.x] = b;
    }
    __syncthreads();

    const int idx = blockIdx.x * 256 + threadIdx.x;   // over NF*NALL/4
    const int f   = idx >> 13;                        // / (NALL/4)
    const int wi  = idx & (NALL / 4 - 1);
    const int4* __restrict__ at4 = (const int4*)(atype + f * NALL);

    int4 a = at4[wi];
    uint32_t o = s_tb[a.x] | (s_tb[a.y] << 8) | (s_tb[a.z] << 16) | (s_tb[a.w] << 24);
    ((uint32_t*)g_byte[f])[wi] = o;

    if (wi == 0) {                                 // virtual atom j == NALL
        uint32_t v = s_tb[NTYPES];                 // byte for type-8 virtual nbr
        #pragma unroll
        for (int k = 0; k < 16; ++k)
            g_byte[f][NALL + k] = (uint8_t)(k == 0 ? v : 0);
    }
}

// ---------------- kernel 2: stream the mask ----------------
static constexpr int THREADS_B = 512;
static constexpr int BPF       = 128;                      // blocks per frame
static constexpr int ROWS_PB   = NLOC / BPF;               // 128 rows / block
static constexpr int ROW_VEC   = NNEI / 4;                 // 32 vec4 per row
static constexpr int VEC_PB    = ROWS_PB * ROW_VEC;        // 4096
static constexpr int ITERS     = VEC_PB / THREADS_B;       // 8
static constexpr int BLOCKS_B  = NF * BPF;                 // 512

static constexpr int SMEM_DYN  = TBL_BYTES;                // 32.8 KB

__global__ __launch_bounds__(THREADS_B, 2)
void mask_kernel(const int4* __restrict__ nlist4,
                 const int*  __restrict__ atype,
                 const float* __restrict__ tmask,
                 uint4* __restrict__ out4)
{
    extern __shared__ uint8_t s_byte[];            // [TBL_BYTES] mask bytes
    __shared__ uint32_t s_rw[16];                  // per-type 9-bit row word
    __shared__ uint32_t s_rowinfo[ROWS_PB];        // (flag<<16) | (1<<ti)

    const int tid  = threadIdx.x;
    const int f    = blockIdx.x >> 7;              // / BPF
    const int row0 = (blockIdx.x & (BPF - 1)) * ROWS_PB;

    // ---- overlapped prologue: issue ALL global loads up front ----
    // (a) table-copy loads (4+ per thread, independent)
    uint4 treg[4];
    const uint4* __restrict__ tsrc = (const uint4*)g_byte[f];
    #pragma unroll
    for (int k = 0; k < 4; ++k)
        treg[k] = tsrc[tid + k * THREADS_B];       // covers 2048 of 2049

    // (b) this block's center types (in flight with (a))
    int my_ti = 0;
    if (tid < ROWS_PB) my_ti = __ldg(atype + f * NALL + row0 + tid);

    // (c) per-type row words from tmask (in flight with (a),(b))
    if (tid < TM1) {
        uint32_t w = 0;
        #pragma unroll
        for (int tj = 0; tj < TM1; ++tj)
            w |= (__ldg(tmask + tid * TM1 + tj) != 0.0f ? 1u : 0u) << tj;
        s_rw[tid] = w;
    }

    // store the table while rw/atype finish
    uint4* tdst = (uint4*)s_byte;
    #pragma unroll
    for (int k = 0; k < 4; ++k)
        tdst[tid + k * THREADS_B] = treg[k];
    if (tid == 0) tdst[2048] = tsrc[2048];         // tail (virtual atom + pad)

    __syncthreads();                               // s_rw ready
    if (tid < ROWS_PB) {
        const uint32_t rw = s_rw[my_ti];
        const uint32_t flag = (rw == FULL) ? 1u : ((rw == 0u) ? 0u : 2u);
        s_rowinfo[tid] = (flag << 16) | (1u << my_ti);
    }
    __syncthreads();                               // table + rowinfo ready

    const size_t base = ((size_t)f * NLOC + row0) * ROW_VEC;
    const int4*  __restrict__ nl = nlist4 + base;
    uint4*       __restrict__ ob = out4  + base;

    // ---- pass A: all row words (LDS broadcast, one row per warp) ----
    uint32_t info[ITERS];
    #pragma unroll
    for (int k = 0; k < ITERS; ++k)
        info[k] = s_rowinfo[(tid + k * THREADS_B) >> 5];

    // ---- pass B: all predicated nlist loads, front-batched (MLP=8) ----
    int4 nj[ITERS];
    #pragma unroll
    for (int k = 0; k < ITERS; ++k)
        if ((info[k] >> 16) == 2u)
            nj[k] = nl[tid + k * THREADS_B];

    // ---- pass C: gather + store ----
    #pragma unroll
    for (int k = 0; k < ITERS; ++k) {
        const int v = tid + k * THREADS_B;
        const uint32_t flag = info[k] >> 16;

        if (flag == 1u) { ob[v] = make_uint4(ONEF, ONEF, ONEF, ONEF); continue; }
        if (flag == 0u) { ob[v] = make_uint4(0u, 0u, 0u, 0u);         continue; }

        const uint32_t m = info[k] & 0xFFFFu;      // 1 << ti (warp-uniform)

        uint32_t j0 = min((uint32_t)nj[k].x, (uint32_t)NALL);
        uint32_t j1 = min((uint32_t)nj[k].y, (uint32_t)NALL);
        uint32_t j2 = min((uint32_t)nj[k].z, (uint32_t)NALL);
        uint32_t j3 = min((uint32_t)nj[k].w, (uint32_t)NALL);

        uint32_t b0 = s_byte[j0];
        uint32_t b1 = s_byte[j1];
        uint32_t b2 = s_byte[j2];
        uint32_t b3 = s_byte[j3];

        uint4 r;
        r.x = (b0 & m) ? ONEF : 0u;
        r.y = (b1 & m) ? ONEF : 0u;
        r.z = (b2 & m) ? ONEF : 0u;
        r.w = (b3 & m) ? ONEF : 0u;

        ob[v] = r;
    }
}

extern "C" void kernel_launch(void* const* d_in, const int* in_sizes, int n_in,
                              void* d_out, int out_size)
{
    const int4*  nlist4 = (const int4*) d_in[0];
    const int*   atype  = (const int*)  d_in[1];
    const float* tmask  = (const float*)d_in[2];
    // d_in[3] = ntypes scalar (8, baked into constants)

    uint4* out4 = (uint4*)d_out;

    static bool configured = false;
    if (!configured) {
        cudaFuncSetAttribute(mask_kernel,
                             cudaFuncAttributeMaxDynamicSharedMemorySize,
                             SMEM_DYN);
        cudaFuncSetAttribute(mask_kernel,
                             cudaFuncAttributePreferredSharedMemoryCarveout,
                             100);
        configured = true;
    }

    pack_kernel<<<NF * NALL / 4 / 256, 256>>>(atype, tmask);
    mask_kernel<<<BLOCKS_B, THREADS_B, SMEM_DYN>>>(nlist4, atype, tmask, out4);
}

// round 9
// speedup vs baseline: 1.1775x; 1.1575x over previous
#include <cuda_runtime.h>
#include <cuda_bf16.h>
#include <cstdint>

// PairExcludeMask: out[f,i,n] = type_mask[ atype[f,i]*9 + tj ]
//   tj = (nlist[f,i,n] == -1) ? 8 : atype[f, nlist[f,i,n]]
//
// pack_kernel: per atom j, byte B[j] with bit ti = (type_mask[ti*9+type_j] != 0).
// mask_kernel: 32KB per-frame byte table pulled into dynamic smem by ONE
// cp.async.bulk (mbarrier-completed, overlapped with rowinfo setup).
// One warp per row -> warp-uniform m = 1<<ti; all-pass/all-fail rows are
// written as constants without reading nlist. Slow path per neighbor:
//   LDS.U8 B[j]; (B & m) ? 1.0f : 0.0f

static constexpr int NF     = 4;
static constexpr int NLOC   = 16384;
static constexpr int NNEI   = 128;
static constexpr int NALL   = 32768;
static constexpr int NTYPES = 8;
static constexpr int TM1    = NTYPES + 1;          // 9
static constexpr uint32_t FULL = (1u << TM1) - 1;  // 0x1FF
static constexpr uint32_t ONEF = 0x3F800000u;      // 1.0f bits

static constexpr int TBL_BYTES = NALL + 16;        // 32784 (16B multiple)

__device__ __align__(16) uint8_t g_byte[NF][TBL_BYTES];

// ---------------- kernel 1: per-atom mask byte ----------------
__global__ __launch_bounds__(256)
void pack_kernel(const int* __restrict__ atype, const float* __restrict__ tmask)
{
    __shared__ uint32_t s_tb[16];                  // per-type mask byte
    if (threadIdx.x < TM1) {
        uint32_t b = 0;
        #pragma unroll
        for (int ti = 0; ti < NTYPES; ++ti)        // centers have ti < 8
            b |= (tmask[ti * TM1 + threadIdx.x] != 0.0f ? 1u : 0u) << ti;
        s_tb[threadIdx.x] = b;
    }
    __syncthreads();

    const int idx = blockIdx.x * 256 + threadIdx.x;   // over NF*NALL/4
    const int f   = idx >> 13;                        // / (NALL/4)
    const int wi  = idx & (NALL / 4 - 1);
    const int4* __restrict__ at4 = (const int4*)(atype + f * NALL);

    int4 a = at4[wi];
    uint32_t o = s_tb[a.x] | (s_tb[a.y] << 8) | (s_tb[a.z] << 16) | (s_tb[a.w] << 24);
    ((uint32_t*)g_byte[f])[wi] = o;

    if (wi == 0) {                                 // virtual atom j == NALL
        uint32_t v = s_tb[NTYPES];
        #pragma unroll
        for (int k = 0; k < 16; ++k)
            g_byte[f][NALL + k] = (uint8_t)(k == 0 ? v : 0);
    }
}

// ---------------- kernel 2: stream the mask ----------------
static constexpr int THREADS_B = 512;
static constexpr int BPF       = 256;                      // blocks per frame
static constexpr int ROWS_PB   = NLOC / BPF;               // 64 rows / block
static constexpr int ROW_VEC   = NNEI / 4;                 // 32 vec4 per row
static constexpr int VEC_PB    = ROWS_PB * ROW_VEC;        // 2048
static constexpr int ITERS     = VEC_PB / THREADS_B;       // 4
static constexpr int BLOCKS_B  = NF * BPF;                 // 1024

// dynamic smem: byte table + (mbar, rowinfo) region appended
static constexpr int SMEM_DYN  = TBL_BYTES;                // table only (32.8KB)

__global__ __launch_bounds__(THREADS_B)
void mask_kernel(const int4* __restrict__ nlist4,
                 const int*  __restrict__ atype,
                 const float* __restrict__ tmask,
                 uint4* __restrict__ out4)
{
    extern __shared__ __align__(16) uint8_t s_byte[];   // [TBL_BYTES]
    __shared__ __align__(8) unsigned long long s_mbar;
    __shared__ uint32_t s_rowinfo[ROWS_PB];             // (flag<<16) | (1<<ti)

    const int tid  = threadIdx.x;
    const int f    = blockIdx.x >> 8;              // / BPF
    const int row0 = (blockIdx.x & (BPF - 1)) * ROWS_PB;

    uint32_t mbar_addr;
    asm("{ .reg .u64 t; cvta.to.shared.u64 t, %1; cvt.u32.u64 %0, t; }"
        : "=r"(mbar_addr) : "l"(&s_mbar));
    uint32_t dst_addr;
    asm("{ .reg .u64 t; cvta.to.shared.u64 t, %1; cvt.u32.u64 %0, t; }"
        : "=r"(dst_addr) : "l"(s_byte));

    if (tid == 0)
        asm volatile("mbarrier.init.shared.b64 [%0], 1;" :: "r"(mbar_addr) : "memory");
    __syncthreads();                               // mbarrier visible

    if (tid == 0) {
        asm volatile("mbarrier.arrive.expect_tx.shared.b64 _, [%0], %1;"
                     :: "r"(mbar_addr), "r"((uint32_t)TBL_BYTES) : "memory");
        asm volatile("cp.async.bulk.shared::cluster.global.mbarrier::complete_tx::bytes "
                     "[%0], [%1], %2, [%3];"
                     :: "r"(dst_addr), "l"(g_byte[f]),
                        "r"((uint32_t)TBL_BYTES), "r"(mbar_addr) : "memory");
    }

    // overlapped with the bulk copy: rowinfo straight from gmem (L2 hits)
    if (tid < ROWS_PB) {
        const int ti = __ldg(atype + f * NALL + row0 + tid);
        uint32_t w = 0;
        #pragma unroll
        for (int tj = 0; tj < TM1; ++tj)
            w |= (__ldg(tmask + ti * TM1 + tj) != 0.0f ? 1u : 0u) << tj;
        const uint32_t flag = (w == FULL) ? 1u : ((w == 0u) ? 0u : 2u);
        s_rowinfo[tid] = (flag << 16) | (1u << ti);
    }
    __syncthreads();                               // rowinfo visible

    // wait for the table
    {
        uint32_t done;
        asm volatile(
            "{\n\t.reg .pred p;\n\t"
            "mbarrier.try_wait.parity.acquire.cta.shared::cta.b64 p, [%1], 0;\n\t"
            "selp.b32 %0, 1, 0, p;\n\t}"
            : "=r"(done) : "r"(mbar_addr) : "memory");
        while (!done) {
            asm volatile(
                "{\n\t.reg .pred p;\n\t"
                "mbarrier.try_wait.parity.acquire.cta.shared::cta.b64 p, [%1], 0, 0x989680;\n\t"
                "selp.b32 %0, 1, 0, p;\n\t}"
                : "=r"(done) : "r"(mbar_addr) : "memory");
        }
    }

    const size_t base = ((size_t)f * NLOC + row0) * ROW_VEC;
    const int4*  __restrict__ nl = nlist4 + base;
    uint4*       __restrict__ ob = out4  + base;

    // ---- pass A: row words (LDS broadcast; one row per warp) ----
    uint32_t info[ITERS];
    #pragma unroll
    for (int k = 0; k < ITERS; ++k)
        info[k] = s_rowinfo[(tid + k * THREADS_B) >> 5];

    // ---- pass B: predicated nlist loads, front-batched (MLP=4) ----
    int4 nj[ITERS];
    #pragma unroll
    for (int k = 0; k < ITERS; ++k)
        if ((info[k] >> 16) == 2u)
            nj[k] = nl[tid + k * THREADS_B];

    // ---- pass C: gather + store ----
    #pragma unroll
    for (int k = 0; k < ITERS; ++k) {
        const int v = tid + k * THREADS_B;
        const uint32_t flag = info[k] >> 16;

        if (flag == 1u) { ob[v] = make_uint4(ONEF, ONEF, ONEF, ONEF); continue; }
        if (flag == 0u) { ob[v] = make_uint4(0u, 0u, 0u, 0u);         continue; }

        const uint32_t m = info[k] & 0xFFFFu;      // 1 << ti (warp-uniform)

        uint32_t j0 = min((uint32_t)nj[k].x, (uint32_t)NALL);
        uint32_t j1 = min((uint32_t)nj[k].y, (uint32_t)NALL);
        uint32_t j2 = min((uint32_t)nj[k].z, (uint32_t)NALL);
        uint32_t j3 = min((uint32_t)nj[k].w, (uint32_t)NALL);

        uint32_t b0 = s_byte[j0];
        uint32_t b1 = s_byte[j1];
        uint32_t b2 = s_byte[j2];
        uint32_t b3 = s_byte[j3];

        uint4 r;
        r.x = (b0 & m) ? ONEF : 0u;
        r.y = (b1 & m) ? ONEF : 0u;
        r.z = (b2 & m) ? ONEF : 0u;
        r.w = (b3 & m) ? ONEF : 0u;

        ob[v] = r;
    }
}

extern "C" void kernel_launch(void* const* d_in, const int* in_sizes, int n_in,
                              void* d_out, int out_size)
{
    const int4*  nlist4 = (const int4*) d_in[0];
    const int*   atype  = (const int*)  d_in[1];
    const float* tmask  = (const float*)d_in[2];
    // d_in[3] = ntypes scalar (8, baked into constants)

    uint4* out4 = (uint4*)d_out;

    static bool configured = false;
    if (!configured) {
        cudaFuncSetAttribute(mask_kernel,
                             cudaFuncAttributeMaxDynamicSharedMemorySize,
                             SMEM_DYN);
        cudaFuncSetAttribute(mask_kernel,
                             cudaFuncAttributePreferredSharedMemoryCarveout,
                             100);
        configured = true;
    }

    pack_kernel<<<NF * NALL / 4 / 256, 256>>>(atype, tmask);
    mask_kernel<<<BLOCKS_B, THREADS_B, SMEM_DYN>>>(nlist4, atype, tmask, out4);
}